// round 5
// baseline (speedup 1.0000x reference)
#include <cuda_runtime.h>
#include <math.h>
#include <stdint.h>

#define B_ 8
#define L_ 1024
#define D_ 256
#define U_ 256

typedef unsigned long long ull;

// ---------------- scratch (device globals; no allocation allowed) ----------
__device__ float g_EW[D_ * U_];          // E @ Wx            (256 KB)
__device__ float g_rnorm[B_ * L_];       // 1/max(rowsum,eps) (32 KB)
__device__ float g_t[B_ * L_ * U_];      // (seq@EW)*rnorm    (8 MB)
__device__ float g_xproj[B_ * L_ * U_];  // G^T @ t           (8 MB)

// ---------------- packed f32x2 helpers (sm_103a) ----------------------------
__device__ __forceinline__ ull pk2(float lo, float hi) {
    ull r; asm("mov.b64 %0,{%1,%2};" : "=l"(r) : "f"(lo), "f"(hi)); return r;
}
__device__ __forceinline__ void ffma2(ull& d, ull a, ull b) {
    asm("fma.rn.f32x2 %0,%1,%2,%0;" : "+l"(d) : "l"(a), "l"(b));
}
__device__ __forceinline__ float2 up2(ull a) {
    float lo, hi; asm("mov.b64 {%0,%1},%2;" : "=f"(lo), "=f"(hi) : "l"(a));
    float2 r; r.x = lo; r.y = hi; return r;
}
// tanh(z) = 1 - 2/(1+exp(2z)) via MUFU (rel err ~1e-6; validated R3/R4)
__device__ __forceinline__ float fast_tanh(float z) {
    float t2 = z * 2.885390081777927f;  // 2*log2(e)
    float ex; asm("ex2.approx.f32 %0,%1;" : "=f"(ex) : "f"(t2));
    float den = ex + 1.0f;
    float rc; asm("rcp.approx.f32 %0,%1;" : "=f"(rc) : "f"(den));
    return fmaf(-2.0f, rc, 1.0f);
}

// ---------------- cluster / mbarrier primitives ------------------------------
__device__ __forceinline__ uint32_t smem_u32(const void* p) {
    return (uint32_t)__cvta_generic_to_shared(p);
}
__device__ __forceinline__ uint32_t my_ctarank() {
    uint32_t r; asm("mov.u32 %0, %%cluster_ctarank;" : "=r"(r)); return r;
}
__device__ __forceinline__ uint32_t mapa_peer(uint32_t addr, uint32_t peer) {
    uint32_t r;
    asm volatile("mapa.shared::cluster.u32 %0, %1, %2;" : "=r"(r) : "r"(addr), "r"(peer));
    return r;
}
__device__ __forceinline__ void st_cluster_f32(uint32_t raddr, float v) {
    asm volatile("st.shared::cluster.f32 [%0], %1;" :: "r"(raddr), "f"(v) : "memory");
}
__device__ __forceinline__ void mbar_init(uint32_t addr, uint32_t cnt) {
    asm volatile("mbarrier.init.shared.b64 [%0], %1;" :: "r"(addr), "r"(cnt) : "memory");
}
__device__ __forceinline__ void mbar_arrive_local(uint32_t addr) {
    asm volatile("mbarrier.arrive.release.cta.shared::cta.b64 _, [%0];"
                 :: "r"(addr) : "memory");
}
__device__ __forceinline__ void mbar_arrive_remote(uint32_t raddr) {
    asm volatile("mbarrier.arrive.release.cluster.shared::cluster.b64 _, [%0];"
                 :: "r"(raddr) : "memory");
}
__device__ __forceinline__ void mbar_wait_cluster(uint32_t addr, uint32_t parity) {
    asm volatile(
        "{\n\t.reg .pred P;\n"
        "WAITLP%=:\n\t"
        "mbarrier.try_wait.parity.acquire.cluster.shared::cta.b64 P, [%0], %1;\n\t"
        "@!P bra WAITLP%=;\n\t}"
        :: "r"(addr), "r"(parity) : "memory");
}
__device__ __forceinline__ void cluster_sync_() {
    asm volatile("barrier.cluster.arrive.aligned;" ::: "memory");
    asm volatile("barrier.cluster.wait.aligned;" ::: "memory");
}

// ---------------- 1) rnorm[b,l] = 1 / max(sum_m graph[b,l,m], 1e-7) ---------
__global__ __launch_bounds__(256) void norm_kernel(const float* __restrict__ graph,
                                                   float* __restrict__ rnorm) {
    int warp = (blockIdx.x * blockDim.x + threadIdx.x) >> 5;
    int lane = threadIdx.x & 31;
    if (warp >= B_ * L_) return;
    const float4* row = (const float4*)(graph + (size_t)warp * L_);
    float s = 0.f;
#pragma unroll
    for (int i = lane; i < L_ / 4; i += 32) {
        float4 v = row[i];
        s += (v.x + v.y) + (v.z + v.w);
    }
#pragma unroll
    for (int o = 16; o; o >>= 1) s += __shfl_xor_sync(0xffffffffu, s, o);
    if (lane == 0) rnorm[warp] = 1.f / fmaxf(s, 1e-7f);
}

// ---------------- 2) GEMM NN (R2 version): 128x128 tile, BK=16 --------------
__global__ __launch_bounds__(256) void gemm_nn(const float* __restrict__ A,
                                               const float* __restrict__ Bm,
                                               float* __restrict__ C, int K,
                                               const float* __restrict__ rowscale) {
    __shared__ float As[2][16][128];
    __shared__ float Bs[2][16][128];
    const int N = 256;
    const int m0 = blockIdx.y * 128, n0 = blockIdx.x * 128;
    const int t = threadIdx.x;
    const int tx = t & 15, ty = t >> 4;

    ull acc[8][4];
#pragma unroll
    for (int i = 0; i < 8; i++)
#pragma unroll
        for (int j = 0; j < 4; j++) acc[i][j] = 0ull;

    int am[2], akg[2], bkk[2], bng[2];
#pragma unroll
    for (int i = 0; i < 2; i++) {
        int f4 = t + i * 256;
        am[i] = f4 >> 2; akg[i] = f4 & 3;
        bkk[i] = f4 >> 5; bng[i] = f4 & 31;
    }

    float4 ra[2], rb[2];
#pragma unroll
    for (int i = 0; i < 2; i++) {
        ra[i] = *(const float4*)(A + (size_t)(m0 + am[i]) * K + akg[i] * 4);
        rb[i] = *(const float4*)(Bm + (size_t)bkk[i] * N + n0 + bng[i] * 4);
    }

    int cur = 0;
    for (int k0 = 0; k0 < K; k0 += 16) {
#pragma unroll
        for (int i = 0; i < 2; i++) {
            As[cur][akg[i] * 4 + 0][am[i]] = ra[i].x;
            As[cur][akg[i] * 4 + 1][am[i]] = ra[i].y;
            As[cur][akg[i] * 4 + 2][am[i]] = ra[i].z;
            As[cur][akg[i] * 4 + 3][am[i]] = ra[i].w;
            *(float4*)&Bs[cur][bkk[i]][bng[i] * 4] = rb[i];
        }
        __syncthreads();
        if (k0 + 16 < K) {
#pragma unroll
            for (int i = 0; i < 2; i++) {
                ra[i] = *(const float4*)(A + (size_t)(m0 + am[i]) * K + k0 + 16 + akg[i] * 4);
                rb[i] = *(const float4*)(Bm + (size_t)(k0 + 16 + bkk[i]) * N + n0 + bng[i] * 4);
            }
        }
#pragma unroll
        for (int kk = 0; kk < 16; kk++) {
            float4 a0 = *(float4*)&As[cur][kk][ty * 8];
            float4 a1 = *(float4*)&As[cur][kk][ty * 8 + 4];
            float4 b0 = *(float4*)&Bs[cur][kk][tx * 8];
            float4 b1 = *(float4*)&Bs[cur][kk][tx * 8 + 4];
            ull bp0 = pk2(b0.x, b0.y), bp1 = pk2(b0.z, b0.w);
            ull bp2 = pk2(b1.x, b1.y), bp3 = pk2(b1.z, b1.w);
            float av[8] = {a0.x, a0.y, a0.z, a0.w, a1.x, a1.y, a1.z, a1.w};
#pragma unroll
            for (int i = 0; i < 8; i++) {
                ull ad = pk2(av[i], av[i]);
                ffma2(acc[i][0], ad, bp0);
                ffma2(acc[i][1], ad, bp1);
                ffma2(acc[i][2], ad, bp2);
                ffma2(acc[i][3], ad, bp3);
            }
        }
        cur ^= 1;
    }
#pragma unroll
    for (int i = 0; i < 8; i++) {
        int row = m0 + ty * 8 + i;
        float sc = rowscale ? rowscale[row] : 1.f;
        float2 v0 = up2(acc[i][0]), v1 = up2(acc[i][1]);
        float2 v2 = up2(acc[i][2]), v3 = up2(acc[i][3]);
        float4 o0 = make_float4(v0.x * sc, v0.y * sc, v1.x * sc, v1.y * sc);
        float4 o1 = make_float4(v2.x * sc, v2.y * sc, v3.x * sc, v3.y * sc);
        *(float4*)(C + (size_t)row * N + n0 + tx * 8) = o0;
        *(float4*)(C + (size_t)row * N + n0 + tx * 8 + 4) = o1;
    }
}

// ---------------- 3) GEMM TN (R2 version): per batch, 128x128 tile ----------
__global__ __launch_bounds__(256) void gemm_tn(const float* __restrict__ A,
                                               const float* __restrict__ Bm,
                                               float* __restrict__ C) {
    __shared__ float As[2][16][128];
    __shared__ float Bs[2][16][128];
    const int N = 256, K = L_, lda = L_;
    const int b = blockIdx.z;
    A += (size_t)b * L_ * L_;
    Bm += (size_t)b * L_ * U_;
    C += (size_t)b * L_ * U_;
    const int m0 = blockIdx.y * 128, n0 = blockIdx.x * 128;
    const int t = threadIdx.x;
    const int tx = t & 15, ty = t >> 4;

    ull acc[8][4];
#pragma unroll
    for (int i = 0; i < 8; i++)
#pragma unroll
        for (int j = 0; j < 4; j++) acc[i][j] = 0ull;

    int kk_[2], g_[2];
#pragma unroll
    for (int i = 0; i < 2; i++) {
        int f4 = t + i * 256;
        kk_[i] = f4 >> 5; g_[i] = f4 & 31;
    }

    float4 ra[2], rb[2];
#pragma unroll
    for (int i = 0; i < 2; i++) {
        ra[i] = *(const float4*)(A + (size_t)kk_[i] * lda + m0 + g_[i] * 4);
        rb[i] = *(const float4*)(Bm + (size_t)kk_[i] * N + n0 + g_[i] * 4);
    }

    int cur = 0;
    for (int k0 = 0; k0 < K; k0 += 16) {
#pragma unroll
        for (int i = 0; i < 2; i++) {
            *(float4*)&As[cur][kk_[i]][g_[i] * 4] = ra[i];
            *(float4*)&Bs[cur][kk_[i]][g_[i] * 4] = rb[i];
        }
        __syncthreads();
        if (k0 + 16 < K) {
#pragma unroll
            for (int i = 0; i < 2; i++) {
                ra[i] = *(const float4*)(A + (size_t)(k0 + 16 + kk_[i]) * lda + m0 + g_[i] * 4);
                rb[i] = *(const float4*)(Bm + (size_t)(k0 + 16 + kk_[i]) * N + n0 + g_[i] * 4);
            }
        }
#pragma unroll
        for (int kk = 0; kk < 16; kk++) {
            float4 a0 = *(float4*)&As[cur][kk][ty * 8];
            float4 a1 = *(float4*)&As[cur][kk][ty * 8 + 4];
            float4 b0 = *(float4*)&Bs[cur][kk][tx * 8];
            float4 b1 = *(float4*)&Bs[cur][kk][tx * 8 + 4];
            ull bp0 = pk2(b0.x, b0.y), bp1 = pk2(b0.z, b0.w);
            ull bp2 = pk2(b1.x, b1.y), bp3 = pk2(b1.z, b1.w);
            float av[8] = {a0.x, a0.y, a0.z, a0.w, a1.x, a1.y, a1.z, a1.w};
#pragma unroll
            for (int i = 0; i < 8; i++) {
                ull ad = pk2(av[i], av[i]);
                ffma2(acc[i][0], ad, bp0);
                ffma2(acc[i][1], ad, bp1);
                ffma2(acc[i][2], ad, bp2);
                ffma2(acc[i][3], ad, bp3);
            }
        }
        cur ^= 1;
    }
#pragma unroll
    for (int i = 0; i < 8; i++) {
        int row = m0 + ty * 8 + i;
        float2 v0 = up2(acc[i][0]), v1 = up2(acc[i][1]);
        float2 v2 = up2(acc[i][2]), v3 = up2(acc[i][3]);
        float4 o0 = make_float4(v0.x, v0.y, v1.x, v1.y);
        float4 o1 = make_float4(v2.x, v2.y, v3.x, v3.y);
        *(float4*)(C + (size_t)row * N + n0 + tx * 8) = o0;
        *(float4*)(C + (size_t)row * N + n0 + tx * 8 + 4) = o1;
    }
}

// ---------------- 4) scan: 2-CTA cluster per batch, all-RF weights ----------
// Cluster of 2 CTAs per batch (grid 16). CTA rank r owns outputs
// u in [r*128, r*128+128). 256 threads: kh = tid>>7 (0 = own h half,
// 1 = peer h half), uloc = tid&127. Each thread: 1 output, 128 k values,
// 64 f32x2 weight pairs ALL in registers. Per step:
//   - kh1 warps wait (mbarrier, acquire.cluster) for peer h half
//   - both kh compute 64 ffma2 dot; kh1 stores partial to SMEM
//   - __syncthreads; kh0 combines, tanh, writes h to local + peer SMEM
//     (st.shared::cluster) and arrives local + remote (release.cluster)
//   - __syncthreads
__global__ __launch_bounds__(256, 1) __cluster_dims__(2, 1, 1)
void scan_kernel(const float* __restrict__ Wh,
                 const float* __restrict__ xproj,
                 const float* __restrict__ bias,
                 float* __restrict__ out) {
    __shared__ __align__(16) float hbuf[2][256];
    __shared__ float part[128];
    __shared__ __align__(8) ull mbar;

    const int tid = threadIdx.x;
    const uint32_t rank = my_ctarank();
    const uint32_t peer = 1u - rank;
    const int b = blockIdx.x >> 1;
    const int kh = tid >> 7;          // 0 = own half, 1 = peer half
    const int uloc = tid & 127;
    const int u = (int)rank * 128 + uloc;
    const int kbase = (kh ? (int)peer : (int)rank) * 128;

    const uint32_t mbar_a = smem_u32(&mbar);
    const uint32_t rmbar = mapa_peer(mbar_a, peer);

    if (tid == 0) mbar_init(mbar_a, 256);
    hbuf[0][tid] = 0.f;
    hbuf[1][tid] = 0.f;

    // weights: wreg[p] = (Wh[kbase+2p][u], Wh[kbase+2p+1][u])
    ull wreg[64];
#pragma unroll
    for (int p = 0; p < 64; p++) {
        int k = kbase + 2 * p;
        wreg[p] = pk2(Wh[(size_t)k * U_ + u], Wh[(size_t)(k + 1) * U_ + u]);
    }

    float bv = 0.f, xv = 0.f;
    const float* xp = xproj + (size_t)b * L_ * U_ + u;
    float* op = out + (size_t)b * L_ * U_ + u;
    if (kh == 0) {
        bv = bias[u];
        xv = xp[0];
    }

    __syncthreads();
    cluster_sync_();  // mbar init + hbuf zeros visible cluster-wide

    uint32_t parity = 0;
    int cur = 0;

    for (int s = 0; s < L_; s++) {
        if (kh == 1 && s > 0) {       // peer-half warps wait for remote h
            mbar_wait_cluster(mbar_a, parity);
            parity ^= 1;
        }
        float xn = 0.f;
        if (kh == 0) {
            int sn = (s + 1 < L_) ? s + 1 : s;
            xn = __ldg(xp + (size_t)sn * U_);
        }

        const ulonglong2* hp = (const ulonglong2*)&hbuf[cur][kbase];
        ull a0 = 0ull, a1 = 0ull, a2 = 0ull, a3 = 0ull;
#pragma unroll
        for (int i = 0; i < 16; i++) {
            ulonglong2 h0 = hp[2 * i];
            ulonglong2 h1 = hp[2 * i + 1];
            ffma2(a0, h0.x, wreg[4 * i + 0]);
            ffma2(a1, h0.y, wreg[4 * i + 1]);
            ffma2(a2, h1.x, wreg[4 * i + 2]);
            ffma2(a3, h1.y, wreg[4 * i + 3]);
        }
        float2 v0 = up2(a0), v1 = up2(a1), v2 = up2(a2), v3 = up2(a3);
        float sum = ((v0.x + v0.y) + (v1.x + v1.y)) +
                    ((v2.x + v2.y) + (v3.x + v3.y));

        if (kh == 1) part[uloc] = sum;
        __syncthreads();

        int nxt = cur ^ 1;
        if (kh == 0) {
            float z = sum + part[uloc] + xv + bv;
            float h = fast_tanh(z);
            hbuf[nxt][u] = h;  // own half locally
            // same slot in peer's hbuf
            uint32_t raddr = mapa_peer(smem_u32(&hbuf[nxt][u]), peer);
            st_cluster_f32(raddr, h);
            op[(size_t)s * U_] = h;
            xv = xn;
            mbar_arrive_local(mbar_a);
            mbar_arrive_remote(rmbar);
        }
        __syncthreads();
        cur = nxt;
    }

    cluster_sync_();  // no CTA exits while peer stores may be in flight
}

// ---------------- launch --------------------------------------------------
extern "C" void kernel_launch(void* const* d_in, const int* in_sizes, int n_in,
                              void* d_out, int out_size) {
    const float* seq = (const float*)d_in[0];    // (8,1024,256)
    const float* graph = (const float*)d_in[1];  // (8,1024,1024)
    const float* E = (const float*)d_in[2];      // (256,256)
    const float* Wx = (const float*)d_in[3];     // (256,256)
    const float* Wh = (const float*)d_in[4];     // (256,256)
    const float* bias = (const float*)d_in[5];   // (256,)
    float* out = (float*)d_out;                  // (8,1024,256)

    float *ew, *rn, *tt, *xp;
    cudaGetSymbolAddress((void**)&ew, g_EW);
    cudaGetSymbolAddress((void**)&rn, g_rnorm);
    cudaGetSymbolAddress((void**)&tt, g_t);
    cudaGetSymbolAddress((void**)&xp, g_xproj);

    norm_kernel<<<(B_ * L_) / 8, 256>>>(graph, rn);
    // EW = E @ Wx (256x256x256)
    gemm_nn<<<dim3(2, 2), 256>>>(E, Wx, ew, 256, nullptr);
    // t = (seq @ EW) * rnorm   (M=8192, K=256, N=256)
    gemm_nn<<<dim3(2, 64), 256>>>(seq, ew, tt, 256, rn);
    // xproj[b] = G[b]^T @ t[b] (per batch M=1024, K=1024, N=256)
    gemm_tn<<<dim3(2, 8, 8), 256>>>(graph, tt, xp);
    // scan: 2 CTAs per batch, cluster (2,1,1)
    scan_kernel<<<2 * B_, 256>>>(Wh, xp, bias, out);
}

// round 6
// speedup vs baseline: 1.2890x; 1.2890x over previous
#include <cuda_runtime.h>
#include <math.h>

#define B_ 8
#define L_ 1024
#define D_ 256
#define U_ 256

typedef unsigned long long ull;

// ---------------- scratch (device globals; no allocation allowed) ----------
__device__ float g_EW[D_ * U_];          // E @ Wx            (256 KB)
__device__ float g_rnorm[B_ * L_];       // 1/max(rowsum,eps) (32 KB)
__device__ float g_t[B_ * L_ * U_];      // (seq@EW)*rnorm    (8 MB)
__device__ float g_xp0[B_ * L_ * U_];    // G^T @ t, K in [0,512)   (8 MB)
__device__ float g_xp1[B_ * L_ * U_];    // G^T @ t, K in [512,1024) (8 MB)

// ---------------- packed f32x2 helpers (sm_103a) ----------------------------
__device__ __forceinline__ ull pk2(float lo, float hi) {
    ull r; asm("mov.b64 %0,{%1,%2};" : "=l"(r) : "f"(lo), "f"(hi)); return r;
}
__device__ __forceinline__ void ffma2(ull& d, ull a, ull b) {
    asm("fma.rn.f32x2 %0,%1,%2,%0;" : "+l"(d) : "l"(a), "l"(b));
}
__device__ __forceinline__ float2 up2(ull a) {
    float lo, hi; asm("mov.b64 {%0,%1},%2;" : "=f"(lo), "=f"(hi) : "l"(a));
    float2 r; r.x = lo; r.y = hi; return r;
}
// tanh(z) = 1 - 2/(1+exp(2z)) via MUFU (rel err ~1e-6; validated R3-R5)
__device__ __forceinline__ float fast_tanh(float z) {
    float t2 = z * 2.885390081777927f;  // 2*log2(e)
    float ex; asm("ex2.approx.f32 %0,%1;" : "=f"(ex) : "f"(t2));
    float den = ex + 1.0f;
    float rc; asm("rcp.approx.f32 %0,%1;" : "=f"(rc) : "f"(den));
    return fmaf(-2.0f, rc, 1.0f);
}

// ---------------- 1) rnorm[b,l] = 1 / max(sum_m graph[b,l,m], 1e-7) ---------
__global__ __launch_bounds__(256) void norm_kernel(const float* __restrict__ graph,
                                                   float* __restrict__ rnorm) {
    int warp = (blockIdx.x * blockDim.x + threadIdx.x) >> 5;
    int lane = threadIdx.x & 31;
    if (warp >= B_ * L_) return;
    const float4* row = (const float4*)(graph + (size_t)warp * L_);
    float s = 0.f;
#pragma unroll
    for (int i = lane; i < L_ / 4; i += 32) {
        float4 v = row[i];
        s += (v.x + v.y) + (v.z + v.w);
    }
#pragma unroll
    for (int o = 16; o; o >>= 1) s += __shfl_xor_sync(0xffffffffu, s, o);
    if (lane == 0) rnorm[warp] = 1.f / fmaxf(s, 1e-7f);
}

// ---------------- 2) GEMM NN (R2 version): 128x128 tile, BK=16 --------------
__global__ __launch_bounds__(256) void gemm_nn(const float* __restrict__ A,
                                               const float* __restrict__ Bm,
                                               float* __restrict__ C, int K,
                                               const float* __restrict__ rowscale) {
    __shared__ float As[2][16][128];
    __shared__ float Bs[2][16][128];
    const int N = 256;
    const int m0 = blockIdx.y * 128, n0 = blockIdx.x * 128;
    const int t = threadIdx.x;
    const int tx = t & 15, ty = t >> 4;

    ull acc[8][4];
#pragma unroll
    for (int i = 0; i < 8; i++)
#pragma unroll
        for (int j = 0; j < 4; j++) acc[i][j] = 0ull;

    int am[2], akg[2], bkk[2], bng[2];
#pragma unroll
    for (int i = 0; i < 2; i++) {
        int f4 = t + i * 256;
        am[i] = f4 >> 2; akg[i] = f4 & 3;
        bkk[i] = f4 >> 5; bng[i] = f4 & 31;
    }

    float4 ra[2], rb[2];
#pragma unroll
    for (int i = 0; i < 2; i++) {
        ra[i] = *(const float4*)(A + (size_t)(m0 + am[i]) * K + akg[i] * 4);
        rb[i] = *(const float4*)(Bm + (size_t)bkk[i] * N + n0 + bng[i] * 4);
    }

    int cur = 0;
    for (int k0 = 0; k0 < K; k0 += 16) {
#pragma unroll
        for (int i = 0; i < 2; i++) {
            As[cur][akg[i] * 4 + 0][am[i]] = ra[i].x;
            As[cur][akg[i] * 4 + 1][am[i]] = ra[i].y;
            As[cur][akg[i] * 4 + 2][am[i]] = ra[i].z;
            As[cur][akg[i] * 4 + 3][am[i]] = ra[i].w;
            *(float4*)&Bs[cur][bkk[i]][bng[i] * 4] = rb[i];
        }
        __syncthreads();
        if (k0 + 16 < K) {
#pragma unroll
            for (int i = 0; i < 2; i++) {
                ra[i] = *(const float4*)(A + (size_t)(m0 + am[i]) * K + k0 + 16 + akg[i] * 4);
                rb[i] = *(const float4*)(Bm + (size_t)(k0 + 16 + bkk[i]) * N + n0 + bng[i] * 4);
            }
        }
#pragma unroll
        for (int kk = 0; kk < 16; kk++) {
            float4 a0 = *(float4*)&As[cur][kk][ty * 8];
            float4 a1 = *(float4*)&As[cur][kk][ty * 8 + 4];
            float4 b0 = *(float4*)&Bs[cur][kk][tx * 8];
            float4 b1 = *(float4*)&Bs[cur][kk][tx * 8 + 4];
            ull bp0 = pk2(b0.x, b0.y), bp1 = pk2(b0.z, b0.w);
            ull bp2 = pk2(b1.x, b1.y), bp3 = pk2(b1.z, b1.w);
            float av[8] = {a0.x, a0.y, a0.z, a0.w, a1.x, a1.y, a1.z, a1.w};
#pragma unroll
            for (int i = 0; i < 8; i++) {
                ull ad = pk2(av[i], av[i]);
                ffma2(acc[i][0], ad, bp0);
                ffma2(acc[i][1], ad, bp1);
                ffma2(acc[i][2], ad, bp2);
                ffma2(acc[i][3], ad, bp3);
            }
        }
        cur ^= 1;
    }
#pragma unroll
    for (int i = 0; i < 8; i++) {
        int row = m0 + ty * 8 + i;
        float sc = rowscale ? rowscale[row] : 1.f;
        float2 v0 = up2(acc[i][0]), v1 = up2(acc[i][1]);
        float2 v2 = up2(acc[i][2]), v3 = up2(acc[i][3]);
        float4 o0 = make_float4(v0.x * sc, v0.y * sc, v1.x * sc, v1.y * sc);
        float4 o1 = make_float4(v2.x * sc, v2.y * sc, v3.x * sc, v3.y * sc);
        *(float4*)(C + (size_t)row * N + n0 + tx * 8) = o0;
        *(float4*)(C + (size_t)row * N + n0 + tx * 8 + 4) = o1;
    }
}

// ---------------- 3) GEMM TN, K-split 2: C_ks[m,u] = sum_{l in half ks} ----
// grid (2, 8, 16): z = b*2 + ks. Same 128x128/8x8 shape as R2 (proven).
__global__ __launch_bounds__(256) void gemm_tn(const float* __restrict__ A,
                                               const float* __restrict__ Bm,
                                               float* __restrict__ C0,
                                               float* __restrict__ C1) {
    __shared__ float As[2][16][128];
    __shared__ float Bs[2][16][128];
    const int N = 256, lda = L_;
    const int bz = blockIdx.z;
    const int b = bz >> 1, ks = bz & 1;
    const int kbeg = ks * (L_ / 2), kend = kbeg + (L_ / 2);
    const float* Ab = A + (size_t)b * L_ * L_;
    const float* Bb = Bm + (size_t)b * L_ * U_;
    float* C = (ks ? C1 : C0) + (size_t)b * L_ * U_;
    const int m0 = blockIdx.y * 128, n0 = blockIdx.x * 128;
    const int t = threadIdx.x;
    const int tx = t & 15, ty = t >> 4;

    ull acc[8][4];
#pragma unroll
    for (int i = 0; i < 8; i++)
#pragma unroll
        for (int j = 0; j < 4; j++) acc[i][j] = 0ull;

    int kk_[2], g_[2];
#pragma unroll
    for (int i = 0; i < 2; i++) {
        int f4 = t + i * 256;
        kk_[i] = f4 >> 5; g_[i] = f4 & 31;
    }

    float4 ra[2], rb[2];
#pragma unroll
    for (int i = 0; i < 2; i++) {
        ra[i] = *(const float4*)(Ab + (size_t)(kbeg + kk_[i]) * lda + m0 + g_[i] * 4);
        rb[i] = *(const float4*)(Bb + (size_t)(kbeg + kk_[i]) * N + n0 + g_[i] * 4);
    }

    int cur = 0;
    for (int k0 = kbeg; k0 < kend; k0 += 16) {
#pragma unroll
        for (int i = 0; i < 2; i++) {
            *(float4*)&As[cur][kk_[i]][g_[i] * 4] = ra[i];
            *(float4*)&Bs[cur][kk_[i]][g_[i] * 4] = rb[i];
        }
        __syncthreads();
        if (k0 + 16 < kend) {
#pragma unroll
            for (int i = 0; i < 2; i++) {
                ra[i] = *(const float4*)(Ab + (size_t)(k0 + 16 + kk_[i]) * lda + m0 + g_[i] * 4);
                rb[i] = *(const float4*)(Bb + (size_t)(k0 + 16 + kk_[i]) * N + n0 + g_[i] * 4);
            }
        }
#pragma unroll
        for (int kk = 0; kk < 16; kk++) {
            float4 a0 = *(float4*)&As[cur][kk][ty * 8];
            float4 a1 = *(float4*)&As[cur][kk][ty * 8 + 4];
            float4 b0 = *(float4*)&Bs[cur][kk][tx * 8];
            float4 b1 = *(float4*)&Bs[cur][kk][tx * 8 + 4];
            ull bp0 = pk2(b0.x, b0.y), bp1 = pk2(b0.z, b0.w);
            ull bp2 = pk2(b1.x, b1.y), bp3 = pk2(b1.z, b1.w);
            float av[8] = {a0.x, a0.y, a0.z, a0.w, a1.x, a1.y, a1.z, a1.w};
#pragma unroll
            for (int i = 0; i < 8; i++) {
                ull ad = pk2(av[i], av[i]);
                ffma2(acc[i][0], ad, bp0);
                ffma2(acc[i][1], ad, bp1);
                ffma2(acc[i][2], ad, bp2);
                ffma2(acc[i][3], ad, bp3);
            }
        }
        cur ^= 1;
    }
#pragma unroll
    for (int i = 0; i < 8; i++) {
        int row = m0 + ty * 8 + i;
        float2 v0 = up2(acc[i][0]), v1 = up2(acc[i][1]);
        float2 v2 = up2(acc[i][2]), v3 = up2(acc[i][3]);
        float4 o0 = make_float4(v0.x, v0.y, v1.x, v1.y);
        float4 o1 = make_float4(v2.x, v2.y, v3.x, v3.y);
        *(float4*)(C + (size_t)row * N + n0 + tx * 8) = o0;
        *(float4*)(C + (size_t)row * N + n0 + tx * 8 + 4) = o1;
    }
}

// ---------------- 4) sequential scan (exact R2 skeleton, fast_tanh, 2-part x)
#define RF_PAIRS 26
#define SM_PAIRS 6
#define WS_ULLS (SM_PAIRS * 4 * 4 * 64)          // 6144 ull = 48 KB
#define SCAN_SMEM_BYTES (WS_ULLS * 8 + 4 * 256 * 4 + 2 * 256 * 4)

__global__ __launch_bounds__(256, 1) void scan_kernel(const float* __restrict__ Wh,
                                                      const float* __restrict__ xp0g,
                                                      const float* __restrict__ xp1g,
                                                      const float* __restrict__ bias,
                                                      float* __restrict__ out) {
    extern __shared__ unsigned char smraw[];
    ull* ws = (ull*)smraw;                                  // 48 KB weights
    float* part = (float*)(smraw + WS_ULLS * 8);            // 4 KB partials
    float* hbuf = part + 4 * 256;                           // 2 KB h (double buf)

    const int tid = threadIdx.x;
    const int b = blockIdx.x;
    const int w = tid >> 5, l = tid & 31;
    const int ks = w >> 1, oh = w & 1;
    const int u0 = oh * 128 + l * 4;

    for (int idx = tid; idx < WS_ULLS; idx += 256) {
        int e = idx >> 6, r = idx & 63;
        int ps = e >> 4, ksf = (e >> 2) & 3, jf = e & 3;
        int ohf = r >> 5, lf = r & 31;
        int uf = ohf * 128 + lf * 4 + jf;
        int kf = ksf * 64 + 2 * (RF_PAIRS + ps);
        ws[idx] = pk2(Wh[kf * U_ + uf], Wh[(kf + 1) * U_ + uf]);
    }

    ull wreg[4][RF_PAIRS];
#pragma unroll
    for (int j = 0; j < 4; j++)
#pragma unroll
        for (int p = 0; p < RF_PAIRS; p++) {
            int k = ks * 64 + 2 * p;
            wreg[j][p] = pk2(Wh[k * U_ + u0 + j], Wh[(k + 1) * U_ + u0 + j]);
        }

    hbuf[tid] = 0.f;
    hbuf[256 + tid] = 0.f;
    const float bv = bias[tid];
    __syncthreads();

    const float* xp0 = xp0g + (size_t)b * L_ * U_ + tid;
    const float* xp1 = xp1g + (size_t)b * L_ * U_ + tid;
    float* op = out + (size_t)b * L_ * U_ + tid;
    float xv = xp0[0] + xp1[0];
    int cur = 0;

    const ull* wsp = ws + ks * 256 + oh * 32 + l;

    for (int s = 0; s < L_; s++) {
        const ulonglong2* hp2 = (const ulonglong2*)(hbuf + cur * 256 + ks * 64);
        ull a0 = 0ull, a1 = 0ull, a2 = 0ull, a3 = 0ull;
#pragma unroll
        for (int q = 0; q < 13; q++) {   // pairs 0..25 (RF)
            ulonglong2 hv = hp2[q];
            ffma2(a0, hv.x, wreg[0][2 * q]);
            ffma2(a1, hv.x, wreg[1][2 * q]);
            ffma2(a2, hv.x, wreg[2][2 * q]);
            ffma2(a3, hv.x, wreg[3][2 * q]);
            ffma2(a0, hv.y, wreg[0][2 * q + 1]);
            ffma2(a1, hv.y, wreg[1][2 * q + 1]);
            ffma2(a2, hv.y, wreg[2][2 * q + 1]);
            ffma2(a3, hv.y, wreg[3][2 * q + 1]);
        }
#pragma unroll
        for (int qq = 0; qq < 3; qq++) { // pairs 26..31 (SMEM)
            ulonglong2 hv = hp2[13 + qq];
            int ps0 = 2 * qq, ps1 = 2 * qq + 1;
            ffma2(a0, hv.x, wsp[ps0 * 1024 + 0 * 64]);
            ffma2(a1, hv.x, wsp[ps0 * 1024 + 1 * 64]);
            ffma2(a2, hv.x, wsp[ps0 * 1024 + 2 * 64]);
            ffma2(a3, hv.x, wsp[ps0 * 1024 + 3 * 64]);
            ffma2(a0, hv.y, wsp[ps1 * 1024 + 0 * 64]);
            ffma2(a1, hv.y, wsp[ps1 * 1024 + 1 * 64]);
            ffma2(a2, hv.y, wsp[ps1 * 1024 + 2 * 64]);
            ffma2(a3, hv.y, wsp[ps1 * 1024 + 3 * 64]);
        }
        float2 v0 = up2(a0), v1 = up2(a1), v2 = up2(a2), v3 = up2(a3);
        float4 pr = make_float4(v0.x + v0.y, v1.x + v1.y, v2.x + v2.y, v3.x + v3.y);
        *(float4*)&part[ks * 256 + u0] = pr;
        __syncthreads();

        float z = part[tid] + part[256 + tid] + part[512 + tid] + part[768 + tid]
                  + xv + bv;
        float h = fast_tanh(z);
        hbuf[(cur ^ 1) * 256 + tid] = h;
        op[(size_t)s * U_] = h;
        int sn = (s + 1 < L_) ? s + 1 : s;
        xv = xp0[(size_t)sn * U_] + xp1[(size_t)sn * U_];
        cur ^= 1;
        __syncthreads();
    }
}

// ---------------- launch --------------------------------------------------
extern "C" void kernel_launch(void* const* d_in, const int* in_sizes, int n_in,
                              void* d_out, int out_size) {
    const float* seq = (const float*)d_in[0];    // (8,1024,256)
    const float* graph = (const float*)d_in[1];  // (8,1024,1024)
    const float* E = (const float*)d_in[2];      // (256,256)
    const float* Wx = (const float*)d_in[3];     // (256,256)
    const float* Wh = (const float*)d_in[4];     // (256,256)
    const float* bias = (const float*)d_in[5];   // (256,)
    float* out = (float*)d_out;                  // (8,1024,256)

    float *ew, *rn, *tt, *x0, *x1;
    cudaGetSymbolAddress((void**)&ew, g_EW);
    cudaGetSymbolAddress((void**)&rn, g_rnorm);
    cudaGetSymbolAddress((void**)&tt, g_t);
    cudaGetSymbolAddress((void**)&x0, g_xp0);
    cudaGetSymbolAddress((void**)&x1, g_xp1);

    norm_kernel<<<(B_ * L_) / 8, 256>>>(graph, rn);
    // EW = E @ Wx (256x256x256)
    gemm_nn<<<dim3(2, 2), 256>>>(E, Wx, ew, 256, nullptr);
    // t = (seq @ EW) * rnorm   (M=8192, K=256, N=256)
    gemm_nn<<<dim3(2, 64), 256>>>(seq, ew, tt, 256, rn);
    // xproj partials: grid (2, 8, 16), z = b*2 + ks, each K half = 512
    gemm_tn<<<dim3(2, 8, 16), 256>>>(graph, tt, x0, x1);
    // scan (adds the two x partials on the fly)
    cudaFuncSetAttribute(scan_kernel, cudaFuncAttributeMaxDynamicSharedMemorySize,
                         SCAN_SMEM_BYTES);
    scan_kernel<<<B_, 256, SCAN_SMEM_BYTES>>>(Wh, x0, x1, bias, out);
}